// round 14
// baseline (speedup 1.0000x reference)
#include <cuda_runtime.h>
#include <cuda_fp16.h>
#include <cstdint>

#define F    128
#define LB   16
#define RC   (128 + LB + 1)       // 145 window rows incl. zero row
#define WSTR 132                  // padded window row stride (floats)
#define WIN_FLTS (RC * WSTR)      // 19140
#define HB_OFF   WIN_FLTS         // hbuf starts here (float index)
#define HB_FLTS  (32768 / 4)      // 32KB fp16 buffer (128 rows x 16 chunks x 16B)
#define META_OFF (HB_OFF + HB_FLTS)
#define SMEM_BYTES ((META_OFF + 3 * 128) * 4)   // 110,864 B

// B fragment blob: [ks(16)][nt(16)][lane(32)] x uint2 (64KB), L2-resident
__device__ __align__(16) uint2 g_bf[16 * 16 * 32];
__device__ float g_bias[F];

__device__ __forceinline__ uint32_t smem_u32(const void* p) {
    uint32_t a;
    asm("{ .reg .u64 t; cvta.to.shared.u64 t, %1; cvt.u32.u64 %0, t; }" : "=r"(a) : "l"(p));
    return a;
}

__device__ __forceinline__ uint32_t h2u(__half2 h) {
    return *reinterpret_cast<uint32_t*>(&h);
}

__device__ __forceinline__ void mma16(float c[4], uint32_t a0, uint32_t a1, uint32_t a2,
                                      uint32_t a3, uint32_t b0, uint32_t b1) {
    asm volatile(
        "mma.sync.aligned.m16n8k16.row.col.f32.f16.f16.f32 "
        "{%0,%1,%2,%3}, {%4,%5,%6,%7}, {%8,%9}, {%0,%1,%2,%3};\n"
        : "+f"(c[0]), "+f"(c[1]), "+f"(c[2]), "+f"(c[3])
        : "r"(a0), "r"(a1), "r"(a2), "r"(a3), "r"(b0), "r"(b1));
}

__device__ __forceinline__ void ldm4(uint4& d, uint32_t addr) {
    asm volatile("ldmatrix.sync.aligned.m8n8.x4.shared.b16 {%0,%1,%2,%3}, [%4];"
                 : "=r"(d.x), "=r"(d.y), "=r"(d.z), "=r"(d.w) : "r"(addr) : "memory");
}

__device__ __forceinline__ void sts128(uint32_t addr, uint4 u) {
    asm volatile("st.shared.v4.b32 [%0], {%1,%2,%3,%4};"
                 :: "r"(addr), "r"(u.x), "r"(u.y), "r"(u.z), "r"(u.w) : "memory");
}

__device__ __forceinline__ void cpa16(uint32_t sa, const void* g) {
    asm volatile("cp.async.cg.shared.global [%0], [%1], 16;\n" :: "r"(sa), "l"(g));
}
#define CP_COMMIT() asm volatile("cp.async.commit_group;" ::: "memory")
#define CP_WAIT0()  asm volatile("cp.async.wait_group 0;" ::: "memory")

__device__ __forceinline__ uint2 ldg_nc_u2(const uint2* p) {
    uint2 v;
    asm volatile("ld.global.nc.v2.u32 {%0,%1}, [%2];" : "=r"(v.x), "=r"(v.y) : "l"(p));
    return v;
}

__device__ __forceinline__ void stg_cs_f2(float* p, float x, float y) {
    asm volatile("st.global.cs.v2.f32 [%0], {%1,%2};" :: "l"(p), "f"(x), "f"(y) : "memory");
}

// hbuf layout: fp16 [row(128)][chunk(16)] of 8 halves; physical chunk = c8 ^ (row&7).
__device__ __forceinline__ uint32_t hb_addr(uint32_t hb, int row, int c8) {
    return hb + (uint32_t)(row * 16 + (c8 ^ (row & 7))) * 16u;
}

// ====================== k0: weights -> B fragment blob (+bias) ======================
__global__ void k0_prep(const float* __restrict__ Ws, const float* __restrict__ Wn,
                        const float* __restrict__ bs, const float* __restrict__ bn) {
    int i = blockIdx.x * blockDim.x + threadIdx.x;
    if (i < F) g_bias[i] = bs[i] + bn[i];
    if (i >= 16 * 16 * 32) return;
    int lane = i & 31, nt = (i >> 5) & 15, ks = i >> 9;
    int k = ks * 16 + (lane & 3) * 2;
    int n = nt * 8 + (lane >> 2);
    const float* W0 = (k < F) ? (Ws + (size_t)k * F) : (Wn + (size_t)(k - F) * F);
    const float* W8 = (k + 8 < F) ? (Ws + (size_t)(k + 8) * F) : (Wn + (size_t)(k + 8 - F) * F);
    uint2 u;
    u.x = h2u(__floats2half2_rn(W0[n], W0[F + n]));
    u.y = h2u(__floats2half2_rn(W8[n], W8[F + n]));
    g_bf[i] = u;
}

// ====================== fused kernel ======================

extern __shared__ float sm[];

// GEMM over one K=128 half from hbuf. A via batched ldmatrix; B frags from
// global (L2) double-buffered one ks ahead so the ~234cyc L2 latency overlaps
// the 16-mma block + next ldmatrix batch.
__device__ __forceinline__ void gemm_half(uint32_t hb, float acc[4][4][4],
                                          int lane, int wm, int wn, int bks0) {
    const int mat = lane >> 3;
    const int row_off = (mat & 1) * 8 + (lane & 7);
    const int k_half = mat >> 1;
    const uint2* bp = &g_bf[(bks0 * 16 + wn * 4) * 32 + lane];  // +512 per ks
    uint2 b[2][4];
    #pragma unroll
    for (int nt = 0; nt < 4; nt++) b[0][nt] = ldg_nc_u2(bp + nt * 32);
    #pragma unroll
    for (int ks = 0; ks < 8; ks++) {
        const int cur = ks & 1, nxt = cur ^ 1;
        uint4 a[4];
        #pragma unroll
        for (int mi = 0; mi < 4; mi++)
            ldm4(a[mi], hb_addr(hb, wm * 64 + mi * 16 + row_off, ks * 2 + k_half));
        if (ks < 7) {
            #pragma unroll
            for (int nt = 0; nt < 4; nt++)
                b[nxt][nt] = ldg_nc_u2(bp + (ks + 1) * 512 + nt * 32);
        }
        #pragma unroll
        for (int mi = 0; mi < 4; mi++)
            #pragma unroll
            for (int nt = 0; nt < 4; nt++)
                mma16(acc[mi][nt], a[mi].x, a[mi].y, a[mi].z, a[mi].w,
                      b[cur][nt].x, b[cur][nt].y);
    }
}

__global__ void __launch_bounds__(256, 2)
fused_tsage(const float* __restrict__ src, const float* __restrict__ dst,
            const int* __restrict__ dme, const float* __restrict__ deg,
            float* __restrict__ out, int E) {
    float* win = sm;                      // RC x WSTR fp32 window
    int*   smm = reinterpret_cast<int*>(sm + META_OFF);   // m - base + 1 (may be <= 0)
    int*   sms = smm + 128;                               // s - base     (may be <  0)
    float* smv = reinterpret_cast<float*>(sms + 128);

    const int tid = threadIdx.x, wid = tid >> 5, lane = tid & 31;
    const int wm = wid >> 2, wn = wid & 3;
    const int t0 = blockIdx.x * 128;
    const uint32_t sa_win = smem_u32(win);
    const uint32_t hb = sa_win + HB_OFF * 4;

    int base = t0 - LB; if (base < 0) base = 0;
    int end  = t0 + 128; if (end > E) end = E;
    const int R = end - base;

    // ---- Phase A: async window load (rows 1..R) ----
    for (int i = tid; i < R * 32; i += 256) {
        int r = i >> 5, q = i & 31;
        cpa16(sa_win + (uint32_t)(r + 1) * (WSTR * 4) + q * 16,
              src + (size_t)(base + r) * F + (size_t)q * 4);
    }
    CP_COMMIT();

    // zero row 0 + meta (overlaps cp.async)
    if (tid < 33) reinterpret_cast<float4*>(win)[tid] = make_float4(0.f, 0.f, 0.f, 0.f);
    if (tid < 128) {
        int e = t0 + tid;
        int m, s; float inv;
        if (e < E) {
            m = dme[e];
            float dg = deg[e];
            s = m - (int)dg + 1;
            inv = 1.f / (dg + 1.f);
        } else { m = base - 1; s = base; inv = 0.f; }
        smm[tid] = m - base + 1;
        sms[tid] = s - base;
        smv[tid] = inv;
    }

    // ---- Phase B1: stage dst tile -> hbuf fp16 (overlaps cp.async) ----
    #pragma unroll
    for (int i = tid; i < 2048; i += 256) {
        int rr = i >> 4, c8 = i & 15;
        int e = t0 + rr;
        float4 v0 = make_float4(0.f, 0.f, 0.f, 0.f), v1 = v0;
        if (e < E) {
            const float4* p = reinterpret_cast<const float4*>(dst + (size_t)e * F + c8 * 8);
            v0 = p[0]; v1 = p[1];
        }
        uint4 u;
        u.x = h2u(__floats2half2_rn(v0.x, v0.y));
        u.y = h2u(__floats2half2_rn(v0.z, v0.w));
        u.z = h2u(__floats2half2_rn(v1.x, v1.y));
        u.w = h2u(__floats2half2_rn(v1.z, v1.w));
        sts128(hb_addr(hb, rr, c8), u);
    }
    CP_WAIT0();
    __syncthreads();

    // ---- Phase B2/C overlapped: warps 4-7 run dst GEMM (rows 64-127)
    //      while warps 0-3 run the window cumsum, then their dst GEMM ----
    float acc[4][4][4];
    #pragma unroll
    for (int a = 0; a < 4; a++)
        #pragma unroll
        for (int b = 0; b < 4; b++)
            #pragma unroll
            for (int c = 0; c < 4; c++) acc[a][b][c] = 0.f;

    if (wid < 4) {
        // per-column inclusive cumsum over window rows (threads 0..127)
        float run = 0.f;
        float* p = win + WSTR + tid;
        #pragma unroll 8
        for (int r = 0; r < R; r++) { run += p[r * WSTR]; p[r * WSTR] = run; }
        gemm_half(hb, acc, lane, 0, wn, 0);
    } else {
        gemm_half(hb, acc, lane, 1, wn, 0);
    }
    __syncthreads();

    // ---- Phase D1: produce h rows -> hbuf fp16 (overwrites dst stage) ----
    #pragma unroll
    for (int i = tid; i < 2048; i += 256) {
        int rr = i >> 4, c8 = i & 15;
        int   mr  = smm[rr];        // m - base + 1
        int   sr  = sms[rr];        // s - base
        float inv = smv[rr];
        float4 v0, v1;
        if (sr >= 0) {
            // fast path: whole range in window; mr >= sr+1 >= 1
            const float4* pm = reinterpret_cast<const float4*>(win + mr * WSTR + c8 * 8);
            const float4* ps = reinterpret_cast<const float4*>(win + sr * WSTR + c8 * 8);
            float4 a0 = pm[0], a1 = pm[1], s0 = ps[0], s1 = ps[1];
            v0.x = a0.x - s0.x; v0.y = a0.y - s0.y; v0.z = a0.z - s0.z; v0.w = a0.w - s0.w;
            v1.x = a1.x - s1.x; v1.y = a1.y - s1.y; v1.z = a1.z - s1.z; v1.w = a1.w - s1.w;
        } else {
            // slow path: s < base. Window part = CS[max(mr,0)] (row 0 is zeros);
            // global part sums src rows [s, min(m, base-1)].
            int mrc = mr > 0 ? mr : 0;
            const float4* pm = reinterpret_cast<const float4*>(win + mrc * WSTR + c8 * 8);
            v0 = pm[0]; v1 = pm[1];
            int gend = base + (mr < 0 ? mr : 0);   // min(m+1, base)
            for (int g = base + sr; g < gend; g++) {
                const float4* pg = reinterpret_cast<const float4*>(src + (size_t)g * F + c8 * 8);
                float4 a0 = pg[0], a1 = pg[1];
                v0.x += a0.x; v0.y += a0.y; v0.z += a0.z; v0.w += a0.w;
                v1.x += a1.x; v1.y += a1.y; v1.z += a1.z; v1.w += a1.w;
            }
        }
        uint4 u;
        u.x = h2u(__floats2half2_rn(v0.x * inv, v0.y * inv));
        u.y = h2u(__floats2half2_rn(v0.z * inv, v0.w * inv));
        u.z = h2u(__floats2half2_rn(v1.x * inv, v1.y * inv));
        u.w = h2u(__floats2half2_rn(v1.z * inv, v1.w * inv));
        sts128(hb_addr(hb, rr, c8), u);
    }
    __syncthreads();

    // ---- Phase D2: h-half GEMM (B ks 8..15), accumulate ----
    gemm_half(hb, acc, lane, wm, wn, 8);

    // ---- Epilogue: +bias, streaming store ----
    const int r0 = lane >> 2, c00 = (lane & 3) * 2;
    #pragma unroll
    for (int mi = 0; mi < 4; mi++) {
        int rA = t0 + (wm * 4 + mi) * 16 + r0;
        #pragma unroll
        for (int nt = 0; nt < 4; nt++) {
            int col = wn * 32 + nt * 8 + c00;
            float2 bv = *reinterpret_cast<const float2*>(g_bias + col);
            if (rA < E)
                stg_cs_f2(out + (size_t)rA * F + col,
                          acc[mi][nt][0] + bv.x, acc[mi][nt][1] + bv.y);
            if (rA + 8 < E)
                stg_cs_f2(out + (size_t)(rA + 8) * F + col,
                          acc[mi][nt][2] + bv.x, acc[mi][nt][3] + bv.y);
        }
    }
}

// ====================== launch ======================

extern "C" void kernel_launch(void* const* d_in, const int* in_sizes, int n_in,
                              void* d_out, int out_size) {
    const float* src = (const float*)d_in[0];
    const float* dst = (const float*)d_in[1];
    // d_in[2] = dst_ids (unused: seg_start derived from dst_max_eid & dst_deg)
    const int*   dme = (const int*)d_in[3];
    const float* deg = (const float*)d_in[4];
    const float* Ws  = (const float*)d_in[5];
    const float* bs  = (const float*)d_in[6];
    const float* Wn  = (const float*)d_in[7];
    const float* bn  = (const float*)d_in[8];
    float* out = (float*)d_out;

    int E = in_sizes[0] / F;
    int tiles = (E + 127) >> 7;

    k0_prep<<<32, 256>>>(Ws, Wn, bs, bn);

    cudaFuncSetAttribute(fused_tsage,
                         cudaFuncAttributeMaxDynamicSharedMemorySize, SMEM_BYTES);
    fused_tsage<<<tiles, 256, SMEM_BYTES>>>(src, dst, dme, deg, out, E);
}

// round 15
// speedup vs baseline: 1.0823x; 1.0823x over previous
#include <cuda_runtime.h>
#include <cuda_fp16.h>
#include <cstdint>

#define F    128
#define TILE 64
#define LB   16
#define RC   (TILE + LB + 1)      // 81 window rows incl. zero row
#define WSTR 132                  // padded window row stride (floats)
#define WIN_FLTS (RC * WSTR)      // 10692
#define HB_OFF   WIN_FLTS         // hbuf starts here (float index)
#define HB_FLTS  (TILE * 16 * 4)  // 16KB fp16 buffer (64 rows x 16 chunks x 16B)
#define META_OFF (HB_OFF + HB_FLTS)
#define SMEM_BYTES ((META_OFF + 3 * TILE) * 4)   // 59,920 B -> 3 blocks/SM

// B fragment blob: [ks(16)][nt(16)][lane(32)] x uint2 (64KB), L2-resident
__device__ __align__(16) uint2 g_bf[16 * 16 * 32];
__device__ float g_bias[F];

__device__ __forceinline__ uint32_t smem_u32(const void* p) {
    uint32_t a;
    asm("{ .reg .u64 t; cvta.to.shared.u64 t, %1; cvt.u32.u64 %0, t; }" : "=r"(a) : "l"(p));
    return a;
}

__device__ __forceinline__ uint32_t h2u(__half2 h) {
    return *reinterpret_cast<uint32_t*>(&h);
}

__device__ __forceinline__ void mma16(float c[4], uint32_t a0, uint32_t a1, uint32_t a2,
                                      uint32_t a3, uint32_t b0, uint32_t b1) {
    asm volatile(
        "mma.sync.aligned.m16n8k16.row.col.f32.f16.f16.f32 "
        "{%0,%1,%2,%3}, {%4,%5,%6,%7}, {%8,%9}, {%0,%1,%2,%3};\n"
        : "+f"(c[0]), "+f"(c[1]), "+f"(c[2]), "+f"(c[3])
        : "r"(a0), "r"(a1), "r"(a2), "r"(a3), "r"(b0), "r"(b1));
}

__device__ __forceinline__ void ldm4(uint4& d, uint32_t addr) {
    asm volatile("ldmatrix.sync.aligned.m8n8.x4.shared.b16 {%0,%1,%2,%3}, [%4];"
                 : "=r"(d.x), "=r"(d.y), "=r"(d.z), "=r"(d.w) : "r"(addr) : "memory");
}

__device__ __forceinline__ void sts128(uint32_t addr, uint4 u) {
    asm volatile("st.shared.v4.b32 [%0], {%1,%2,%3,%4};"
                 :: "r"(addr), "r"(u.x), "r"(u.y), "r"(u.z), "r"(u.w) : "memory");
}

__device__ __forceinline__ void cpa16(uint32_t sa, const void* g) {
    asm volatile("cp.async.cg.shared.global [%0], [%1], 16;\n" :: "r"(sa), "l"(g));
}
#define CP_COMMIT() asm volatile("cp.async.commit_group;" ::: "memory")
#define CP_WAIT0()  asm volatile("cp.async.wait_group 0;" ::: "memory")

__device__ __forceinline__ uint2 ldg_nc_u2(const uint2* p) {
    uint2 v;
    asm volatile("ld.global.nc.v2.u32 {%0,%1}, [%2];" : "=r"(v.x), "=r"(v.y) : "l"(p));
    return v;
}

__device__ __forceinline__ void stg_cs_f2(float* p, float x, float y) {
    asm volatile("st.global.cs.v2.f32 [%0], {%1,%2};" :: "l"(p), "f"(x), "f"(y) : "memory");
}

// hbuf layout: fp16 [row(64)][chunk(16)] of 8 halves; physical chunk = c8 ^ (row&7).
__device__ __forceinline__ uint32_t hb_addr(uint32_t hb, int row, int c8) {
    return hb + (uint32_t)(row * 16 + (c8 ^ (row & 7))) * 16u;
}

// ====================== k0: weights -> B fragment blob (+bias) ======================
__global__ void k0_prep(const float* __restrict__ Ws, const float* __restrict__ Wn,
                        const float* __restrict__ bs, const float* __restrict__ bn) {
    int i = blockIdx.x * blockDim.x + threadIdx.x;
    if (i < F) g_bias[i] = bs[i] + bn[i];
    if (i >= 16 * 16 * 32) return;
    int lane = i & 31, nt = (i >> 5) & 15, ks = i >> 9;
    int k = ks * 16 + (lane & 3) * 2;
    int n = nt * 8 + (lane >> 2);
    const float* W0 = (k < F) ? (Ws + (size_t)k * F) : (Wn + (size_t)(k - F) * F);
    const float* W8 = (k + 8 < F) ? (Ws + (size_t)(k + 8) * F) : (Wn + (size_t)(k + 8 - F) * F);
    uint2 u;
    u.x = h2u(__floats2half2_rn(W0[n], W0[F + n]));
    u.y = h2u(__floats2half2_rn(W8[n], W8[F + n]));
    g_bf[i] = u;
}

// ====================== fused kernel ======================

extern __shared__ float sm[];

// GEMM over one K=128 half from hbuf (A via ldmatrix) + g_bf B frags (L2).
__device__ __forceinline__ void gemm_half(uint32_t hb, float acc[2][4][4],
                                          int lane, int wm, int wn, int bks0) {
    const int mat = lane >> 3;
    const int row_off = (mat & 1) * 8 + (lane & 7);
    const int k_half = mat >> 1;
    #pragma unroll
    for (int ks = 0; ks < 8; ks++) {
        uint2 b[4];
        #pragma unroll
        for (int nt = 0; nt < 4; nt++)
            b[nt] = ldg_nc_u2(&g_bf[((bks0 + ks) * 16 + wn * 4 + nt) * 32 + lane]);
        #pragma unroll
        for (int mi = 0; mi < 2; mi++) {
            int row = wm * 32 + mi * 16 + row_off;
            uint4 a;
            ldm4(a, hb_addr(hb, row, ks * 2 + k_half));
            #pragma unroll
            for (int nt = 0; nt < 4; nt++)
                mma16(acc[mi][nt], a.x, a.y, a.z, a.w, b[nt].x, b[nt].y);
        }
    }
}

__global__ void __launch_bounds__(256, 3)
fused_tsage(const float* __restrict__ src, const float* __restrict__ dst,
            const int* __restrict__ dme, const float* __restrict__ deg,
            float* __restrict__ out, int E) {
    float* win = sm;                      // RC x WSTR fp32 window
    int*   smm = reinterpret_cast<int*>(sm + META_OFF);   // m - base + 1 (may be <= 0)
    int*   sms = smm + TILE;                              // s - base     (may be <  0)
    float* smv = reinterpret_cast<float*>(sms + TILE);

    const int tid = threadIdx.x, wid = tid >> 5, lane = tid & 31;
    const int wm = wid >> 2, wn = wid & 3;
    const int t0 = blockIdx.x * TILE;
    const uint32_t sa_win = smem_u32(win);
    const uint32_t hb = sa_win + HB_OFF * 4;

    int base = t0 - LB; if (base < 0) base = 0;
    int end  = t0 + TILE; if (end > E) end = E;
    const int R = end - base;

    // ---- Phase A: async window load (rows 1..R) ----
    for (int i = tid; i < R * 32; i += 256) {
        int r = i >> 5, q = i & 31;
        cpa16(sa_win + (uint32_t)(r + 1) * (WSTR * 4) + q * 16,
              src + (size_t)(base + r) * F + (size_t)q * 4);
    }
    CP_COMMIT();

    // zero row 0 + meta (overlaps cp.async)
    if (tid < 33) reinterpret_cast<float4*>(win)[tid] = make_float4(0.f, 0.f, 0.f, 0.f);
    if (tid < TILE) {
        int e = t0 + tid;
        int m, s; float inv;
        if (e < E) {
            m = dme[e];
            float dg = deg[e];
            s = m - (int)dg + 1;
            inv = 1.f / (dg + 1.f);
        } else { m = base - 1; s = base; inv = 0.f; }
        smm[tid] = m - base + 1;
        sms[tid] = s - base;
        smv[tid] = inv;
    }

    // ---- Phase B1: stage dst tile -> hbuf fp16 (overlaps cp.async) ----
    #pragma unroll
    for (int i = tid; i < TILE * 16; i += 256) {
        int rr = i >> 4, c8 = i & 15;
        int e = t0 + rr;
        float4 v0 = make_float4(0.f, 0.f, 0.f, 0.f), v1 = v0;
        if (e < E) {
            const float4* p = reinterpret_cast<const float4*>(dst + (size_t)e * F + c8 * 8);
            v0 = p[0]; v1 = p[1];
        }
        uint4 u;
        u.x = h2u(__floats2half2_rn(v0.x, v0.y));
        u.y = h2u(__floats2half2_rn(v0.z, v0.w));
        u.z = h2u(__floats2half2_rn(v1.x, v1.y));
        u.w = h2u(__floats2half2_rn(v1.z, v1.w));
        sts128(hb_addr(hb, rr, c8), u);
    }
    CP_WAIT0();
    __syncthreads();

    // ---- Phase B2/C overlapped: warps 4-7 run dst GEMM (rows 32-63)
    //      while warps 0-3 run the window cumsum, then their dst GEMM ----
    float acc[2][4][4];
    #pragma unroll
    for (int a = 0; a < 2; a++)
        #pragma unroll
        for (int b = 0; b < 4; b++)
            #pragma unroll
            for (int c = 0; c < 4; c++) acc[a][b][c] = 0.f;

    if (wid < 4) {
        // per-column inclusive cumsum over window rows (threads 0..127)
        float run = 0.f;
        float* p = win + WSTR + tid;
        #pragma unroll 8
        for (int r = 0; r < R; r++) { run += p[r * WSTR]; p[r * WSTR] = run; }
        gemm_half(hb, acc, lane, 0, wn, 0);
    } else {
        gemm_half(hb, acc, lane, 1, wn, 0);
    }
    __syncthreads();

    // ---- Phase D1: produce h rows -> hbuf fp16 (overwrites dst stage) ----
    #pragma unroll
    for (int i = tid; i < TILE * 16; i += 256) {
        int rr = i >> 4, c8 = i & 15;
        int   mr  = smm[rr];        // m - base + 1
        int   sr  = sms[rr];        // s - base
        float inv = smv[rr];
        float4 v0, v1;
        if (sr >= 0) {
            // fast path: whole range in window; mr >= sr+1 >= 1
            const float4* pm = reinterpret_cast<const float4*>(win + mr * WSTR + c8 * 8);
            const float4* ps = reinterpret_cast<const float4*>(win + sr * WSTR + c8 * 8);
            float4 a0 = pm[0], a1 = pm[1], s0 = ps[0], s1 = ps[1];
            v0.x = a0.x - s0.x; v0.y = a0.y - s0.y; v0.z = a0.z - s0.z; v0.w = a0.w - s0.w;
            v1.x = a1.x - s1.x; v1.y = a1.y - s1.y; v1.z = a1.z - s1.z; v1.w = a1.w - s1.w;
        } else {
            // slow path: s < base. Window part = CS[max(mr,0)] (row 0 is zeros);
            // global part sums src rows [s, min(m, base-1)].
            int mrc = mr > 0 ? mr : 0;
            const float4* pm = reinterpret_cast<const float4*>(win + mrc * WSTR + c8 * 8);
            v0 = pm[0]; v1 = pm[1];
            int gend = base + (mr < 0 ? mr : 0);   // min(m+1, base)
            for (int g = base + sr; g < gend; g++) {
                const float4* pg = reinterpret_cast<const float4*>(src + (size_t)g * F + c8 * 8);
                float4 a0 = pg[0], a1 = pg[1];
                v0.x += a0.x; v0.y += a0.y; v0.z += a0.z; v0.w += a0.w;
                v1.x += a1.x; v1.y += a1.y; v1.z += a1.z; v1.w += a1.w;
            }
        }
        uint4 u;
        u.x = h2u(__floats2half2_rn(v0.x * inv, v0.y * inv));
        u.y = h2u(__floats2half2_rn(v0.z * inv, v0.w * inv));
        u.z = h2u(__floats2half2_rn(v1.x * inv, v1.y * inv));
        u.w = h2u(__floats2half2_rn(v1.z * inv, v1.w * inv));
        sts128(hb_addr(hb, rr, c8), u);
    }
    __syncthreads();

    // ---- Phase D2: h-half GEMM (B ks 8..15), accumulate ----
    gemm_half(hb, acc, lane, wm, wn, 8);

    // ---- Epilogue: +bias, streaming store ----
    const int r0 = lane >> 2, c00 = (lane & 3) * 2;
    #pragma unroll
    for (int mi = 0; mi < 2; mi++) {
        int rA = t0 + wm * 32 + mi * 16 + r0;
        #pragma unroll
        for (int nt = 0; nt < 4; nt++) {
            int col = wn * 32 + nt * 8 + c00;
            float2 bv = *reinterpret_cast<const float2*>(g_bias + col);
            if (rA < E)
                stg_cs_f2(out + (size_t)rA * F + col,
                          acc[mi][nt][0] + bv.x, acc[mi][nt][1] + bv.y);
            if (rA + 8 < E)
                stg_cs_f2(out + (size_t)(rA + 8) * F + col,
                          acc[mi][nt][2] + bv.x, acc[mi][nt][3] + bv.y);
        }
    }
}

// ====================== launch ======================

extern "C" void kernel_launch(void* const* d_in, const int* in_sizes, int n_in,
                              void* d_out, int out_size) {
    const float* src = (const float*)d_in[0];
    const float* dst = (const float*)d_in[1];
    // d_in[2] = dst_ids (unused: seg_start derived from dst_max_eid & dst_deg)
    const int*   dme = (const int*)d_in[3];
    const float* deg = (const float*)d_in[4];
    const float* Ws  = (const float*)d_in[5];
    const float* bs  = (const float*)d_in[6];
    const float* Wn  = (const float*)d_in[7];
    const float* bn  = (const float*)d_in[8];
    float* out = (float*)d_out;

    int E = in_sizes[0] / F;
    int tiles = (E + TILE - 1) / TILE;

    k0_prep<<<32, 256>>>(Ws, Wn, bs, bn);

    cudaFuncSetAttribute(fused_tsage,
                         cudaFuncAttributeMaxDynamicSharedMemorySize, SMEM_BYTES);
    fused_tsage<<<tiles, 256, SMEM_BYTES>>>(src, dst, dme, deg, out, E);
}